// round 9
// baseline (speedup 1.0000x reference)
#include <cuda_runtime.h>
#include <cstdint>

// ---------------------------------------------------------------------------
// Fused multi-head attention, one CTA per batch element.
//   x[4096,128,128] -> out[4096,128,128]
//   TF32 mma.sync (m16n8k8) for all 6 GEMM stages, fp32 accumulate.
//   8 warps; warp w owns query rows [16w, 16w+16).
//   R7: per-head O -> SMEM (A-frag layout), packed 3-matrix weight stage,
//       tiled final projection  => no register spills.
// ---------------------------------------------------------------------------

namespace {

constexpr int XST = 132;   // x smem row stride (words)   -> conflict-free A frags
constexpr int KST = 36;    // K smem row stride           -> conflict-free S B frags
constexpr int VST = 40;    // V smem row stride           -> conflict-free PV B frags
constexpr int W3T = 104;   // packed Wq|Wk|Wv row stride  -> conflict-free QKV B frags
constexpr int OST = 132;   // O smem row stride           -> conflict-free proj A frags
constexpr int PST = 136;   // Wp stage stride             -> conflict-free proj B frags

constexpr int XS_OFF = 0;
constexpr int KS_OFF = XS_OFF + 128 * XST;   // 16896
constexpr int VS_OFF = KS_OFF + 128 * KST;   // 21504
constexpr int WB_OFF = VS_OFF + 128 * VST;   // 26624
constexpr int O_OFF  = WB_OFF + 128 * W3T;   // 39936
constexpr int SMEM_WORDS = O_OFF + 128 * OST; // 56832 words = 227328 B
// Wp stage (128*136=17408 words) reuses offset 0 (XS+KS dead by then).
constexpr unsigned SMEM_BYTES = SMEM_WORDS * 4;

__device__ __forceinline__ uint32_t f2tf32(float f) {
  uint32_t r;
  asm("cvt.rna.tf32.f32 %0, %1;" : "=r"(r) : "f"(f));
  return r;
}

__device__ __forceinline__ void mma8(float& d0, float& d1, float& d2, float& d3,
                                     uint32_t a0, uint32_t a1, uint32_t a2, uint32_t a3,
                                     uint32_t b0, uint32_t b1) {
  asm volatile(
      "mma.sync.aligned.m16n8k8.row.col.f32.tf32.tf32.f32 "
      "{%0,%1,%2,%3},{%4,%5,%6,%7},{%8,%9},{%0,%1,%2,%3};"
      : "+f"(d0), "+f"(d1), "+f"(d2), "+f"(d3)
      : "r"(a0), "r"(a1), "r"(a2), "r"(a3), "r"(b0), "r"(b1));
}

// m16n8 C-layout tile -> m16k8 A-layout tile (tf32). 8 shuffles, warp-uniform.
__device__ __forceinline__ void c2a(float c0, float c1, float c2, float c3,
                                    uint32_t a[4]) {
  int lane = threadIdx.x & 31;
  int qi = lane & 3;
  int s1 = (lane & ~3) | (qi >> 1);
  int s2 = s1 + 2;
  float t0 = __shfl_sync(0xffffffffu, c0, s1);
  float t1 = __shfl_sync(0xffffffffu, c1, s1);
  float t2 = __shfl_sync(0xffffffffu, c2, s1);
  float t3 = __shfl_sync(0xffffffffu, c3, s1);
  float u0 = __shfl_sync(0xffffffffu, c0, s2);
  float u1 = __shfl_sync(0xffffffffu, c1, s2);
  float u2 = __shfl_sync(0xffffffffu, c2, s2);
  float u3 = __shfl_sync(0xffffffffu, c3, s2);
  bool odd = (qi & 1);
  a[0] = f2tf32(odd ? t1 : t0);
  a[1] = f2tf32(odd ? t3 : t2);
  a[2] = f2tf32(odd ? u1 : u0);
  a[3] = f2tf32(odd ? u3 : u2);
}

__global__ __launch_bounds__(256, 1)
void mha_fused_kernel(const float* __restrict__ x,
                      const float* __restrict__ Wq, const float* __restrict__ bq,
                      const float* __restrict__ Wk, const float* __restrict__ bk,
                      const float* __restrict__ Wv, const float* __restrict__ bv,
                      const float* __restrict__ Wp, const float* __restrict__ bp,
                      float* __restrict__ out) {
  extern __shared__ uint32_t sm[];
  uint32_t* XS = sm + XS_OFF;
  uint32_t* KS = sm + KS_OFF;
  uint32_t* VS = sm + VS_OFF;
  uint32_t* WB = sm + WB_OFF;
  uint32_t* OS = sm + O_OFF;

  const int tid = threadIdx.x;
  const int lane = tid & 31;
  const int w = tid >> 5;
  const int g = lane >> 2;
  const int qi = lane & 3;
  const int b = blockIdx.x;
  const int row0 = w * 16 + g;
  const int row1 = row0 + 8;

  // ---- stage x -> XS (tf32) ----
  {
    const float4* xg = reinterpret_cast<const float4*>(x) + (size_t)b * 4096;
    #pragma unroll
    for (int i = 0; i < 16; i++) {
      int v = tid + i * 256;
      float4 f = xg[v];
      int t = v >> 5;
      int d = (v & 31) << 2;
      uint32_t* p = XS + t * XST + d;
      p[0] = f2tf32(f.x); p[1] = f2tf32(f.y); p[2] = f2tf32(f.z); p[3] = f2tf32(f.w);
    }
  }

  const int nt_lim = 2 * w + 1;  // last active key tile under causal mask (warp-uniform)
  const float scale = 0.088388347648318447f;  // 128^-0.5 (CONTEXT_SIZE scaling!)

  #pragma unroll
  for (int h = 0; h < 4; h++) {
    __syncthreads();  // prior iteration's K/V/W reads complete

    // ---- stage Wq_h|Wk_h|Wv_h packed -> WB[128][W3T], mat m at col m*32 ----
    {
      const float4* wq4 = reinterpret_cast<const float4*>(Wq + h * 4096);
      const float4* wk4 = reinterpret_cast<const float4*>(Wk + h * 4096);
      const float4* wv4 = reinterpret_cast<const float4*>(Wv + h * 4096);
      #pragma unroll
      for (int i = 0; i < 4; i++) {
        int v = tid + i * 256;       // 0..1023 float4s per matrix
        int d = v >> 3;              // row (D index)
        int n = (v & 7) << 2;        // col within 32
        uint32_t* p = WB + d * W3T + n;
        float4 f;
        f = wq4[v];
        p[0] = f2tf32(f.x); p[1] = f2tf32(f.y); p[2] = f2tf32(f.z); p[3] = f2tf32(f.w);
        f = wk4[v];
        p[32] = f2tf32(f.x); p[33] = f2tf32(f.y); p[34] = f2tf32(f.z); p[35] = f2tf32(f.w);
        f = wv4[v];
        p[64] = f2tf32(f.x); p[65] = f2tf32(f.y); p[66] = f2tf32(f.z); p[67] = f2tf32(f.w);
      }
    }
    __syncthreads();

    // ---- Q,K,V = x @ W (+bias): shared A fragments, 12 MMAs of ILP per kt ----
    float qacc[4][4], kacc[4][4], vacc[4][4];
    #pragma unroll
    for (int nt = 0; nt < 4; nt++) {
      #pragma unroll
      for (int j = 0; j < 4; j++) { qacc[nt][j] = 0.f; kacc[nt][j] = 0.f; vacc[nt][j] = 0.f; }
    }
    #pragma unroll
    for (int kt = 0; kt < 16; kt++) {
      int abase = kt * 8 + qi;
      uint32_t a0 = XS[row0 * XST + abase];
      uint32_t a1 = XS[row1 * XST + abase];
      uint32_t a2 = XS[row0 * XST + abase + 4];
      uint32_t a3 = XS[row1 * XST + abase + 4];
      int brow = (kt * 8 + qi) * W3T;
      #pragma unroll
      for (int nt = 0; nt < 4; nt++) {
        int boff = brow + nt * 8 + g;
        mma8(qacc[nt][0], qacc[nt][1], qacc[nt][2], qacc[nt][3],
             a0, a1, a2, a3, WB[boff], WB[boff + 4 * W3T]);
        mma8(kacc[nt][0], kacc[nt][1], kacc[nt][2], kacc[nt][3],
             a0, a1, a2, a3, WB[boff + 32], WB[boff + 32 + 4 * W3T]);
        mma8(vacc[nt][0], vacc[nt][1], vacc[nt][2], vacc[nt][3],
             a0, a1, a2, a3, WB[boff + 64], WB[boff + 64 + 4 * W3T]);
      }
    }

    // ---- biases, store K/V to smem (tf32); scale Q and convert C->A ----
    uint32_t qa[4][4];
    #pragma unroll
    for (int nt = 0; nt < 4; nt++) {
      int c = nt * 8 + 2 * qi;
      float2 bqv = *reinterpret_cast<const float2*>(bq + h * 32 + c);
      float2 bkv = *reinterpret_cast<const float2*>(bk + h * 32 + c);
      float2 bvv = *reinterpret_cast<const float2*>(bv + h * 32 + c);

      KS[row0 * KST + c]     = f2tf32(kacc[nt][0] + bkv.x);
      KS[row0 * KST + c + 1] = f2tf32(kacc[nt][1] + bkv.y);
      KS[row1 * KST + c]     = f2tf32(kacc[nt][2] + bkv.x);
      KS[row1 * KST + c + 1] = f2tf32(kacc[nt][3] + bkv.y);
      VS[row0 * VST + c]     = f2tf32(vacc[nt][0] + bvv.x);
      VS[row0 * VST + c + 1] = f2tf32(vacc[nt][1] + bvv.y);
      VS[row1 * VST + c]     = f2tf32(vacc[nt][2] + bvv.x);
      VS[row1 * VST + c + 1] = f2tf32(vacc[nt][3] + bvv.y);

      c2a((qacc[nt][0] + bqv.x) * scale, (qacc[nt][1] + bqv.y) * scale,
          (qacc[nt][2] + bqv.x) * scale, (qacc[nt][3] + bqv.y) * scale, qa[nt]);
    }
    __syncthreads();

    // ---- streaming attention: S-mma -> exp -> c2a -> PV-mma, no max pass ----
    float oacc[4][4];
    #pragma unroll
    for (int nt = 0; nt < 4; nt++) {
      oacc[nt][0] = 0.f; oacc[nt][1] = 0.f; oacc[nt][2] = 0.f; oacc[nt][3] = 0.f;
    }
    float sum0 = 0.f, sum1 = 0.f;

    #pragma unroll
    for (int nt = 0; nt < 16; nt++) {
      if (nt <= nt_lim) {
        float s0 = 0.f, s1 = 0.f, s2 = 0.f, s3 = 0.f;
        #pragma unroll
        for (int kt = 0; kt < 4; kt++) {
          int boff = (nt * 8 + g) * KST + kt * 8 + qi;
          mma8(s0, s1, s2, s3,
               qa[kt][0], qa[kt][1], qa[kt][2], qa[kt][3],
               KS[boff], KS[boff + 4]);
        }
        int c = nt * 8 + 2 * qi;
        float p0 = (c     > row0) ? 0.f : __expf(s0);
        float p1 = (c + 1 > row0) ? 0.f : __expf(s1);
        float p2 = (c     > row1) ? 0.f : __expf(s2);
        float p3 = (c + 1 > row1) ? 0.f : __expf(s3);
        sum0 += p0 + p1;
        sum1 += p2 + p3;

        uint32_t pa[4];
        c2a(p0, p1, p2, p3, pa);
        int brow = (nt * 8 + qi) * VST;
        #pragma unroll
        for (int ntv = 0; ntv < 4; ntv++) {
          int boff = brow + ntv * 8 + g;
          mma8(oacc[ntv][0], oacc[ntv][1], oacc[ntv][2], oacc[ntv][3],
               pa[0], pa[1], pa[2], pa[3], VS[boff], VS[boff + 4 * VST]);
        }
      }
    }

    // row sums (quad reduce), normalize, write O_h columns to SMEM (tf32)
    sum0 += __shfl_xor_sync(0xffffffffu, sum0, 1);
    sum0 += __shfl_xor_sync(0xffffffffu, sum0, 2);
    sum1 += __shfl_xor_sync(0xffffffffu, sum1, 1);
    sum1 += __shfl_xor_sync(0xffffffffu, sum1, 2);
    float inv0 = __fdividef(1.0f, sum0);
    float inv1 = __fdividef(1.0f, sum1);

    #pragma unroll
    for (int nt = 0; nt < 4; nt++) {
      int c = h * 32 + nt * 8 + 2 * qi;
      OS[row0 * OST + c]     = f2tf32(oacc[nt][0] * inv0);
      OS[row0 * OST + c + 1] = f2tf32(oacc[nt][1] * inv0);
      OS[row1 * OST + c]     = f2tf32(oacc[nt][2] * inv1);
      OS[row1 * OST + c + 1] = f2tf32(oacc[nt][3] * inv1);
    }
  }  // heads

  // ---- final projection: out = O @ Wp + bp (O A-frags from SMEM) ----
  __syncthreads();  // all XS/KS reads done; O fully written
  {
    uint32_t* WpS = sm;  // reuse XS+KS region (dead)
    const float4* wg = reinterpret_cast<const float4*>(Wp);
    #pragma unroll
    for (int i = 0; i < 16; i++) {
      int v = tid + i * 256;
      float4 f = wg[v];
      int d = v >> 5;
      int n = (v & 31) << 2;
      uint32_t* p = WpS + d * PST + n;
      p[0] = f2tf32(f.x); p[1] = f2tf32(f.y); p[2] = f2tf32(f.z); p[3] = f2tf32(f.w);
    }
    __syncthreads();

    float* og = out + (size_t)b * 16384;
    #pragma unroll
    for (int half = 0; half < 2; half++) {
      float acc[8][4];
      #pragma unroll
      for (int nt8 = 0; nt8 < 8; nt8++) {
        int c = (half * 8 + nt8) * 8 + 2 * qi;
        float2 bpv = *reinterpret_cast<const float2*>(bp + c);
        acc[nt8][0] = bpv.x; acc[nt8][1] = bpv.y;
        acc[nt8][2] = bpv.x; acc[nt8][3] = bpv.y;
      }
      #pragma unroll
      for (int kt = 0; kt < 16; kt++) {
        int abase = kt * 8 + qi;
        uint32_t a0 = OS[row0 * OST + abase];
        uint32_t a1 = OS[row1 * OST + abase];
        uint32_t a2 = OS[row0 * OST + abase + 4];
        uint32_t a3 = OS[row1 * OST + abase + 4];
        int brow = (kt * 8 + qi) * PST;
        #pragma unroll
        for (int nt8 = 0; nt8 < 8; nt8++) {
          int boff = brow + (half * 8 + nt8) * 8 + g;
          mma8(acc[nt8][0], acc[nt8][1], acc[nt8][2], acc[nt8][3],
               a0, a1, a2, a3, WpS[boff], WpS[boff + 4 * PST]);
        }
      }
      #pragma unroll
      for (int nt8 = 0; nt8 < 8; nt8++) {
        int c = (half * 8 + nt8) * 8 + 2 * qi;
        *reinterpret_cast<float2*>(og + row0 * 128 + c) = make_float2(acc[nt8][0], acc[nt8][1]);
        *reinterpret_cast<float2*>(og + row1 * 128 + c) = make_float2(acc[nt8][2], acc[nt8][3]);
      }
    }
  }
}

}  // namespace

extern "C" void kernel_launch(void* const* d_in, const int* in_sizes, int n_in,
                              void* d_out, int out_size) {
  const float* x  = (const float*)d_in[0];
  const float* Wq = (const float*)d_in[1];
  const float* bq = (const float*)d_in[2];
  const float* Wk = (const float*)d_in[3];
  const float* bk = (const float*)d_in[4];
  const float* Wv = (const float*)d_in[5];
  const float* bv = (const float*)d_in[6];
  const float* Wp = (const float*)d_in[7];
  const float* bp = (const float*)d_in[8];
  float* out = (float*)d_out;

  int batches = in_sizes[0] / (128 * 128);  // 4096

  cudaFuncSetAttribute(mha_fused_kernel,
                       cudaFuncAttributeMaxDynamicSharedMemorySize, SMEM_BYTES);
  mha_fused_kernel<<<batches, 256, SMEM_BYTES>>>(x, Wq, bq, Wk, bk, Wv, bv, Wp, bp, out);
}